// round 3
// baseline (speedup 1.0000x reference)
#include <cuda_runtime.h>
#include <cuda_bf16.h>
#include <cstdint>

// Problem constants
#define B_    32
#define N_    64
#define H_    32
#define KTOT  1280            // D*E
#define NROWS (B_*N_*N_)      // 131072
#define NP1   65
#define TILE_M 128
#define NTILES (NROWS / TILE_M)   // 1024
#define BK    32              // K chunk
#define NCH   (KTOT / BK)     // 40 chunks
#define SB    1288            // Bs row stride (bf16): 1288/2 % 32 == 4 -> conflict-free
#define SA    40              // As row stride (bf16): 40/2 % 32 == 20 -> conflict-free
#define SMEM_BYTES ((32 * SB + 2 * 128 * SA) * 2)   // 102,912 B

// Scratch (allocation-free contract: device globals)
__device__ __nv_bfloat16 g_M[H_ * KTOT];            // 80 KB folded W3*W_edge, [g][k]
__device__ float         g_ei[(size_t)H_ * NROWS];  // 16.8 MB GEMM out, [h][row] (coalesced consume)

// ---------------------------------------------------------------------------
// Kernel 1: M[g][dd*64+e] = sum_h W3[dd][h][g] * W_edge[h][e]
// ---------------------------------------------------------------------------
__global__ void prep_M(const float* __restrict__ W_edge, const float* __restrict__ edw) {
    int idx = blockIdx.x * blockDim.x + threadIdx.x;
    if (idx >= H_ * KTOT) return;
    int g  = idx / KTOT;
    int k  = idx - g * KTOT;
    int dd = k >> 6;
    int e  = k & 63;
    float s = 0.f;
#pragma unroll
    for (int h = 0; h < 32; h++)
        s += edw[dd * 1024 + h * 32 + g] * W_edge[h * 64 + e];
    g_M[g * KTOT + k] = __float2bfloat16(s);
}

// ---------------------------------------------------------------------------
// Kernel 2: C[131072,32] = A[131072,1280](f32->bf16) x M^T via mma.m16n8k16.
//   A path: coalesced LDG.128 (full lines) -> cvt bf16 -> STS -> LDS fragments.
//   B path: full 80KB M staged once per CTA in SMEM.
// ---------------------------------------------------------------------------
__global__ void __launch_bounds__(256, 2) gemm_k(const float* __restrict__ A) {
    extern __shared__ __nv_bfloat16 sm[];
    __nv_bfloat16* Bs  = sm;                    // [32][SB]
    __nv_bfloat16* As0 = sm + 32 * SB;          // [128][SA]
    __nv_bfloat16* As1 = As0 + 128 * SA;

    const int tid  = threadIdx.x;
    const int warp = tid >> 5;
    const int lane = tid & 31;
    const int q = lane >> 2;
    const int t = lane & 3;

    // ---- stage full B (g_M) into SMEM once ----
    {
        const uint4* src = (const uint4*)g_M;
#pragma unroll
        for (int i = 0; i < 20; i++) {
            int idx = tid + i * 256;            // 0..5119 (32 rows x 160 uint4)
            int g   = idx / 160;
            int c8  = idx - g * 160;
            uint4 v = src[g * 160 + c8];
            *(uint4*)(Bs + g * SB + c8 * 8) = v;
        }
    }

    const int row0 = blockIdx.x * TILE_M;

    // ---- A staging mapping: thread -> (rowA = tid/8 in 0..31, colA = (tid&7)*4) ----
    const int rA = tid >> 3;
    const int cA = (tid & 7) * 4;
    const float* aB = A + (size_t)(row0 + rA) * KTOT + cA;

    uint4 rb0[4], rb1[4];
    auto LDGc = [&](uint4* r, int c) {
        const float* p = aB + c * BK;
#pragma unroll
        for (int ps = 0; ps < 4; ps++)
            r[ps] = *(const uint4*)(p + (size_t)ps * 32 * KTOT);
    };
    auto CVTSTS = [&](const uint4* r, __nv_bfloat16* as) {
#pragma unroll
        for (int ps = 0; ps < 4; ps++) {
            const float* f = (const float*)&r[ps];
            __nv_bfloat162 h0 = __floats2bfloat162_rn(f[0], f[1]);
            __nv_bfloat162 h1 = __floats2bfloat162_rn(f[2], f[3]);
            uint2 pk = make_uint2(*(uint32_t*)&h0, *(uint32_t*)&h1);
            *(uint2*)(as + (ps * 32 + rA) * SA + cA) = pk;
        }
    };

    float acc[4][4];
#pragma unroll
    for (int i = 0; i < 4; i++)
#pragma unroll
        for (int j = 0; j < 4; j++) acc[i][j] = 0.f;

    const __nv_bfloat16* arow0b = nullptr;  // set per chunk buffer
    auto MMAc = [&](const __nv_bfloat16* as, int kg) {
        const __nv_bfloat16* ar0 = as + (warp * 16 + q) * SA + t * 2;
        const __nv_bfloat16* ar1 = ar0 + 8 * SA;
#pragma unroll
        for (int u = 0; u < 2; u++) {
            uint32_t a0 = *(const uint32_t*)(ar0 + u * 16);
            uint32_t a1 = *(const uint32_t*)(ar1 + u * 16);
            uint32_t a2 = *(const uint32_t*)(ar0 + u * 16 + 8);
            uint32_t a3 = *(const uint32_t*)(ar1 + u * 16 + 8);
#pragma unroll
            for (int nb = 0; nb < 4; nb++) {
                const __nv_bfloat16* bp = Bs + (nb * 8 + q) * SB + kg + u * 16 + t * 2;
                uint32_t b0 = *(const uint32_t*)bp;
                uint32_t b1 = *(const uint32_t*)(bp + 8);
                asm volatile(
                    "mma.sync.aligned.m16n8k16.row.col.f32.bf16.bf16.f32 "
                    "{%0,%1,%2,%3}, {%4,%5,%6,%7}, {%8,%9}, {%0,%1,%2,%3};"
                    : "+f"(acc[nb][0]), "+f"(acc[nb][1]),
                      "+f"(acc[nb][2]), "+f"(acc[nb][3])
                    : "r"(a0), "r"(a1), "r"(a2), "r"(a3), "r"(b0), "r"(b1));
            }
        }
    };

    // ---- software pipeline: depth-2 LDG, double-buffered SMEM ----
    LDGc(rb0, 0);
    LDGc(rb1, 1);
    CVTSTS(rb0, As0);
    __syncthreads();                 // also fences B staging

    for (int c = 0; c < NCH; c += 2) {
        if (c + 2 < NCH) LDGc(rb0, c + 2);
        MMAc(As0, c * BK);
        CVTSTS(rb1, As1);
        __syncthreads();
        if (c + 3 < NCH) LDGc(rb1, c + 3);
        MMAc(As1, (c + 1) * BK);
        if (c + 2 < NCH) CVTSTS(rb0, As0);
        __syncthreads();
    }

    // ---- epilogue: write C to g_ei[h][row] (32B sectors fully used) ----
    const int rq  = row0 + warp * 16 + q;
    const int rq8 = rq + 8;
#pragma unroll
    for (int nb = 0; nb < 4; nb++) {
        const int g0 = nb * 8 + t * 2;
        g_ei[(size_t)(g0 + 0) * NROWS + rq ] = acc[nb][0];
        g_ei[(size_t)(g0 + 1) * NROWS + rq ] = acc[nb][1];
        g_ei[(size_t)(g0 + 0) * NROWS + rq8] = acc[nb][2];
        g_ei[(size_t)(g0 + 1) * NROWS + rq8] = acc[nb][3];
    }
}

// ---------------------------------------------------------------------------
// Kernel 3: assemble output (B,H,65,65)
// ---------------------------------------------------------------------------
__global__ void assemble(const float* __restrict__ attn_bias,
                         const int*   __restrict__ spatial_pos,
                         const float* __restrict__ spatial_emb,
                         const float* __restrict__ vd,
                         float*       __restrict__ out) {
    int o = blockIdx.x * blockDim.x + threadIdx.x;
    const int TOT = B_ * H_ * NP1 * NP1;
    if (o >= TOT) return;
    int j   = o % NP1;
    int tmp = o / NP1;
    int i   = tmp % NP1;
    tmp    /= NP1;
    int h   = tmp % H_;
    int b   = tmp / H_;

    float v = 2.f * attn_bias[(b * NP1 + i) * NP1 + j];
    if (i == 0 || j == 0) {
        v += vd[h];
        if (i == 0 && j == 0) v = 2.f * attn_bias[(b * NP1) * NP1] + vd[h];
    } else {
        int p = (b * N_ + (i - 1)) * N_ + (j - 1);
        int s = spatial_pos[p];
        v += spatial_emb[s * H_ + h];
        int sp = (s <= 1) ? 1 : (s - 1);
        sp = min(sp, 20);
        v += g_ei[(size_t)h * NROWS + p] / (float)sp;
    }
    out[o] = v;
}

// ---------------------------------------------------------------------------
extern "C" void kernel_launch(void* const* d_in, const int* in_sizes, int n_in,
                              void* d_out, int out_size) {
    // metadata order: node_features, attn_bias, spatial_pos, edge_input,
    //                 attn_edge_type, W_edge, spatial_emb, vd_weight, edge_dis_weight
    const float* attn_bias   = (const float*)d_in[1];
    const int*   spatial_pos = (const int*)  d_in[2];
    const float* edge_input  = (const float*)d_in[3];
    const float* W_edge      = (const float*)d_in[5];
    const float* spatial_emb = (const float*)d_in[6];
    const float* vd          = (const float*)d_in[7];
    const float* edw         = (const float*)d_in[8];
    float* out = (float*)d_out;

    static bool attr_set = false;
    if (!attr_set) {
        cudaFuncSetAttribute(gemm_k, cudaFuncAttributeMaxDynamicSharedMemorySize, SMEM_BYTES);
        attr_set = true;
    }

    prep_M<<<(H_ * KTOT + 255) / 256, 256>>>(W_edge, edw);
    gemm_k<<<NTILES, 256, SMEM_BYTES>>>(edge_input);
    const int tot = B_ * H_ * NP1 * NP1;
    assemble<<<(tot + 255) / 256, 256>>>(attn_bias, spatial_pos, spatial_emb, vd, out);
}

// round 4
// speedup vs baseline: 1.2110x; 1.2110x over previous
#include <cuda_runtime.h>
#include <cuda_bf16.h>
#include <cstdint>

// Problem constants
#define B_    32
#define N_    64
#define H_    32
#define KTOT  1280            // D*E
#define NROWS (B_*N_*N_)      // 131072
#define NP1   65
#define TILE_M 128
#define NTILES (NROWS / TILE_M)   // 1024
#define KC    320             // K chunk held in SMEM
#define NCHUNKS 4
#define BSTR  328             // SMEM B row stride (bf16 elems): conflict-free LDS pattern

// Scratch (allocation-free contract: device globals)
__device__ __nv_bfloat16 g_M[H_ * KTOT];            // 80 KB folded W3*W_edge, [g][k'] (k-permuted)
__device__ float         g_ei[(size_t)NROWS * H_];  // 16.8 MB GEMM output [row][g]

// ---------------------------------------------------------------------------
// Kernel 1: g_M[g][k'] = M[g][sigma(k')],  M[g][dd*64+e] = sum_h W3[dd][h][g]*W_edge[h][e]
// sigma permutes within each 16-group so that a contiguous LDG.128 float4
// (cols 4t..4t+3) is a valid mma.m16n8k16 A fragment.
// ---------------------------------------------------------------------------
__global__ void prep_M(const float* __restrict__ W_edge, const float* __restrict__ edw) {
    int idx = blockIdx.x * blockDim.x + threadIdx.x;
    if (idx >= H_ * KTOT) return;
    int g  = idx / KTOT;
    int kp = idx - g * KTOT;                 // permuted position k'
    int bse = kp & ~15;
    int b   = kp & 15;
    int o   = (b < 8) ? ((b >> 1) * 4 + (b & 1))
                      : (((b - 8) >> 1) * 4 + 2 + (b & 1));
    int k  = bse + o;                        // original k
    int dd = k >> 6;
    int e  = k & 63;
    float s = 0.f;
#pragma unroll
    for (int h = 0; h < 32; h++)
        s += edw[dd * 1024 + h * 32 + g] * W_edge[h * 64 + e];
    g_M[g * KTOT + kp] = __float2bfloat16(s);
}

// ---------------------------------------------------------------------------
// Kernel 2: C[131072,32] = A[131072,1280](f32->bf16) x M^T, mma.m16n8k16.
// A fragments loaded directly from gmem with LDG.128 (512B/instr at 8 lines).
// ---------------------------------------------------------------------------
__device__ __forceinline__ uint32_t f2b2(float x, float y) {
    __nv_bfloat162 b = __floats2bfloat162_rn(x, y);
    return *reinterpret_cast<uint32_t*>(&b);
}

__global__ void __launch_bounds__(256) gemm_k(const float* __restrict__ A) {
    __shared__ __nv_bfloat16 Bs[2][H_ * BSTR];   // 2 x 21 KB

    const int tid  = threadIdx.x;
    const int warp = tid >> 5;
    const int lane = tid & 31;
    const int q = lane >> 2;      // 0..7
    const int t = lane & 3;       // 0..3
    const int row0 = blockIdx.x * TILE_M + warp * 16;

    // lane's A pointers: row q / row q+8, col base t*4 (16B per LDG.128)
    const float* ap0 = A + (size_t)(row0 + q) * KTOT + t * 4;
    const float* ap1 = ap0 + (size_t)8 * KTOT;

    float acc[4][4];
#pragma unroll
    for (int i = 0; i < 4; i++)
#pragma unroll
        for (int j = 0; j < 4; j++) acc[i][j] = 0.f;

    // stage one K-chunk of (already permuted) M into SMEM
    auto loadB = [&](int chunk, int buf) {
#pragma unroll
        for (int i = 0; i < 5; i++) {
            int idx = tid + i * 256;          // 0..1279 (32 rows x 40 uint4)
            int g   = idx / 40;
            int kq  = idx - g * 40;
            uint4 v = *(const uint4*)(g_M + g * KTOT + chunk * KC + kq * 8);
            *(uint4*)(&Bs[buf][g * BSTR + kq * 8]) = v;
        }
    };

    // prefetch one k32 group: 4 x LDG.128 per lane
    float4 f[2][2][2];   // [buf][u][rowhalf]
    auto loadA = [&](float4 (&dst)[2][2], int kc) {
#pragma unroll
        for (int u = 0; u < 2; u++) {
            dst[u][0] = *(const float4*)(ap0 + kc + u * 16);
            dst[u][1] = *(const float4*)(ap1 + kc + u * 16);
        }
    };

    loadB(0, 0);
    loadA(f[0], 0);
    __syncthreads();

    for (int c = 0; c < NCHUNKS; c++) {
        if (c + 1 < NCHUNKS) loadB(c + 1, (c + 1) & 1);
        const __nv_bfloat16* bs = Bs[c & 1];
#pragma unroll
        for (int s2 = 0; s2 < 10; s2++) {          // k32 double-steps
            const int kc    = c * KC + s2 * 32;
            const int knext = kc + 32;
            const int cur   = s2 & 1;
            if (knext < KTOT) loadA(f[cur ^ 1], knext);
#pragma unroll
            for (int u = 0; u < 2; u++) {
                const int ks = (kc - c * KC) + u * 16;   // smem col base (permuted k')
                float4 fq  = f[cur][u][0];
                float4 fq8 = f[cur][u][1];
                // contiguous float4 = fragment (k' = 2t,2t+1 | 2t+8,2t+9) via sigma
                uint32_t a0 = f2b2(fq.x,  fq.y);
                uint32_t a1 = f2b2(fq8.x, fq8.y);
                uint32_t a2 = f2b2(fq.z,  fq.w);
                uint32_t a3 = f2b2(fq8.z, fq8.w);
#pragma unroll
                for (int nb = 0; nb < 4; nb++) {
                    const __nv_bfloat16* bp = bs + (nb * 8 + q) * BSTR + ks + t * 2;
                    uint32_t b0 = *(const uint32_t*)bp;
                    uint32_t b1 = *(const uint32_t*)(bp + 8);
                    asm volatile(
                        "mma.sync.aligned.m16n8k16.row.col.f32.bf16.bf16.f32 "
                        "{%0,%1,%2,%3}, {%4,%5,%6,%7}, {%8,%9}, {%0,%1,%2,%3};"
                        : "+f"(acc[nb][0]), "+f"(acc[nb][1]),
                          "+f"(acc[nb][2]), "+f"(acc[nb][3])
                        : "r"(a0), "r"(a1), "r"(a2), "r"(a3), "r"(b0), "r"(b1));
                }
            }
        }
        __syncthreads();
    }

    // C fragment: c0,c1 -> (row q, g 2t..2t+1); c2,c3 -> (row q+8)
#pragma unroll
    for (int nb = 0; nb < 4; nb++) {
        const int gc = nb * 8 + t * 2;
        *(float2*)&g_ei[(size_t)(row0 + q)     * H_ + gc] = make_float2(acc[nb][0], acc[nb][1]);
        *(float2*)&g_ei[(size_t)(row0 + q + 8) * H_ + gc] = make_float2(acc[nb][2], acc[nb][3]);
    }
}

// ---------------------------------------------------------------------------
// Kernel 3: assemble output (B,H,65,65)
// ---------------------------------------------------------------------------
__global__ void assemble(const float* __restrict__ attn_bias,
                         const int*   __restrict__ spatial_pos,
                         const float* __restrict__ spatial_emb,
                         const float* __restrict__ vd,
                         float*       __restrict__ out) {
    int o = blockIdx.x * blockDim.x + threadIdx.x;
    const int TOT = B_ * H_ * NP1 * NP1;
    if (o >= TOT) return;
    int j   = o % NP1;
    int tmp = o / NP1;
    int i   = tmp % NP1;
    tmp    /= NP1;
    int h   = tmp % H_;
    int b   = tmp / H_;

    float v = 2.f * attn_bias[(b * NP1 + i) * NP1 + j];
    if (i == 0) {
        v += vd[h];
    } else if (j == 0) {
        v += vd[h];
    } else {
        int p = (b * N_ + (i - 1)) * N_ + (j - 1);
        int s = spatial_pos[p];
        v += spatial_emb[s * H_ + h];
        int sp = (s <= 1) ? 1 : (s - 1);
        sp = min(sp, 20);
        v += g_ei[(size_t)p * H_ + h] / (float)sp;
    }
    out[o] = v;
}

// ---------------------------------------------------------------------------
extern "C" void kernel_launch(void* const* d_in, const int* in_sizes, int n_in,
                              void* d_out, int out_size) {
    // metadata order: node_features, attn_bias, spatial_pos, edge_input,
    //                 attn_edge_type, W_edge, spatial_emb, vd_weight, edge_dis_weight
    const float* attn_bias   = (const float*)d_in[1];
    const int*   spatial_pos = (const int*)  d_in[2];
    const float* edge_input  = (const float*)d_in[3];
    const float* W_edge      = (const float*)d_in[5];
    const float* spatial_emb = (const float*)d_in[6];
    const float* vd          = (const float*)d_in[7];
    const float* edw         = (const float*)d_in[8];
    float* out = (float*)d_out;

    prep_M<<<(H_ * KTOT + 255) / 256, 256>>>(W_edge, edw);
    gemm_k<<<NTILES, 256>>>(edge_input);
    const int tot = B_ * H_ * NP1 * NP1;
    assemble<<<(tot + 255) / 256, 256>>>(attn_bias, spatial_pos, spatial_emb, vd, out);
}